// round 2
// baseline (speedup 1.0000x reference)
#include <cuda_runtime.h>
#include <math.h>

#define BB 2
#define NN 512
#define DD 64
#define HH 8
#define DHH 128

#define OFF_ELOG   0
#define OFF_WE     4160
#define OFF_WG     4672
#define OFF_WOE    5184
#define OFF_W1     5696
#define OFF_W2     13888
#define OFF_B1     22080
#define OFF_B2     22208
#define OFF_Q      22272
#define OFF_G1     22336
#define OFF_BE1    22400
#define OFF_G2     22464
#define OFF_BE2    22528
#define OFF_CENT   22592
#define OFF_WPART  22600
#define SMEM_FLOATS 22664
#define SMEM_BYTES  (SMEM_FLOATS * 4)

__device__ __align__(16) float g_n1[BB*NN*DD];
__device__ __align__(16) float g_q [BB*NN*DD];
__device__ __align__(16) float g_k [BB*NN*DD];
__device__ __align__(16) float g_v [BB*NN*DD];
__device__ __align__(16) float g_vc[BB*NN*DD];

__global__ void k_node_prep(const float* __restrict__ n,
                            const float* __restrict__ Wq,
                            const float* __restrict__ Wk,
                            const float* __restrict__ Wv,
                            const float* __restrict__ lng,
                            const float* __restrict__ lnb)
{
    int row = blockIdx.x;
    int o = threadIdx.x;
    __shared__ float sx[DD];
    __shared__ float sn1[DD];
    sx[o] = n[row*DD + o];
    __syncthreads();
    float s = 0.f;
    #pragma unroll
    for (int k = 0; k < DD; k++) s += sx[k];
    float m = s * (1.f/DD);
    float v = 0.f;
    #pragma unroll
    for (int k = 0; k < DD; k++) { float d = sx[k]-m; v += d*d; }
    v *= (1.f/DD);
    float rstd = rsqrtf(v + 1e-5f);
    float n1 = (sx[o]-m)*rstd*lng[o] + lnb[o];
    sn1[o] = n1;
    g_n1[row*DD + o] = n1;
    __syncthreads();
    float q = 0.f, kk = 0.f, vv = 0.f;
    #pragma unroll
    for (int k = 0; k < DD; k++) {
        float a = sn1[k];
        q  += a * Wq[k*DD + o];
        kk += a * Wk[k*DD + o];
        vv += a * Wv[k*DD + o];
    }
    g_q[row*DD + o] = q;
    g_k[row*DD + o] = kk;
    g_v[row*DD + o] = vv;
}

__global__ void __launch_bounds__(256, 1)
k_edge(const float* __restrict__ e,
       const float* __restrict__ We, const float* __restrict__ Wg,
       const float* __restrict__ WoE,
       const float* __restrict__ lg1, const float* __restrict__ lb1,
       const float* __restrict__ lg2, const float* __restrict__ lb2,
       const float* __restrict__ W1, const float* __restrict__ Bi1,
       const float* __restrict__ W2, const float* __restrict__ Bi2,
       float* __restrict__ e_out)
{
    extern __shared__ float sm[];
    float* sElog  = sm + OFF_ELOG;
    float* sWe    = sm + OFF_WE;
    float* sWg    = sm + OFF_WG;
    float* sWoE   = sm + OFF_WOE;
    float* sW1    = sm + OFF_W1;
    float* sW2    = sm + OFF_W2;
    float* sB1    = sm + OFF_B1;
    float* sB2    = sm + OFF_B2;
    float* sQ     = sm + OFF_Q;
    float* sG1    = sm + OFF_G1;
    float* sBe1   = sm + OFF_BE1;
    float* sG2    = sm + OFF_G2;
    float* sBe2   = sm + OFF_BE2;
    float* sCent  = sm + OFF_CENT;
    float* sWpart = sm + OFF_WPART;

    const int i   = blockIdx.x;
    const int b   = blockIdx.y;
    const int tid = threadIdx.x;
    const int lane = tid & 31;
    const int warp = tid >> 5;
    const int rowbn = b*NN + i;

    for (int t = tid; t < 512; t += 256) {
        sWe[t] = We[t]; sWg[t] = Wg[t]; sWoE[t] = WoE[t];
    }
    for (int t = tid; t < 8192; t += 256) {
        int k = t >> 7, u = t & 127;
        sW1[u*64 + k] = W1[t];
        sW2[t] = W2[t];
    }
    if (tid < 128) sB1[tid] = Bi1[tid];
    if (tid < 64) {
        sB2[tid]  = Bi2[tid];
        sQ[tid]   = g_q[rowbn*DD + tid];
        sG1[tid]  = lg1[tid]; sBe1[tid] = lb1[tid];
        sG2[tid]  = lg2[tid]; sBe2[tid] = lb2[tid];
    }
    __syncthreads();

    const float* erow = e + (size_t)rowbn * NN * DD;
    const float scale = 0.35355339059327373f;

    float gacc[HH];
    #pragma unroll
    for (int h = 0; h < HH; h++) gacc[h] = 0.f;

    #pragma unroll
    for (int jj = 0; jj < 2; jj++) {
        const int j = tid + jj*256;
        float4 x4[16];
        const float4* xp = (const float4*)(erow + j*DD);
        #pragma unroll
        for (int q = 0; q < 16; q++) x4[q] = xp[q];

        float s0=0,s1=0,s2=0,s3=0;
        #pragma unroll
        for (int q = 0; q < 16; q++) { s0+=x4[q].x; s1+=x4[q].y; s2+=x4[q].z; s3+=x4[q].w; }
        float m = ((s0+s1)+(s2+s3)) * (1.f/64.f);
        float v0=0,v1=0,v2=0,v3=0;
        #pragma unroll
        for (int q = 0; q < 16; q++) {
            float dx=x4[q].x-m, dy=x4[q].y-m, dz=x4[q].z-m, dw=x4[q].w-m;
            v0+=dx*dx; v1+=dy*dy; v2+=dz*dz; v3+=dw*dw;
        }
        float rstd = rsqrtf(((v0+v1)+(v2+v3))*(1.f/64.f) + 1e-5f);

        float Eh[HH], Gh[HH];
        #pragma unroll
        for (int h = 0; h < HH; h++) { Eh[h]=0.f; Gh[h]=0.f; }
        #pragma unroll
        for (int q = 0; q < 16; q++) {
            float xs[4] = {x4[q].x, x4[q].y, x4[q].z, x4[q].w};
            #pragma unroll
            for (int c = 0; c < 4; c++) {
                int k = q*4 + c;
                float e1 = (xs[c]-m)*rstd*sG1[k] + sBe1[k];
                const float4* we = (const float4*)(sWe + k*8);
                const float4* wg = (const float4*)(sWg + k*8);
                float4 a0 = we[0], a1 = we[1];
                float4 c0 = wg[0], c1 = wg[1];
                Eh[0]+=e1*a0.x; Eh[1]+=e1*a0.y; Eh[2]+=e1*a0.z; Eh[3]+=e1*a0.w;
                Eh[4]+=e1*a1.x; Eh[5]+=e1*a1.y; Eh[6]+=e1*a1.z; Eh[7]+=e1*a1.w;
                Gh[0]+=e1*c0.x; Gh[1]+=e1*c0.y; Gh[2]+=e1*c0.z; Gh[3]+=e1*c0.w;
                Gh[4]+=e1*c1.x; Gh[5]+=e1*c1.y; Gh[6]+=e1*c1.z; Gh[7]+=e1*c1.w;
            }
        }

        float ac[HH];
        #pragma unroll
        for (int h = 0; h < HH; h++) ac[h] = 0.f;
        const float4* kp = (const float4*)(g_k + (b*NN + j)*DD);
        const float4* qp = (const float4*)sQ;
        #pragma unroll
        for (int q = 0; q < 16; q++) {
            float4 kv = kp[q], qv = qp[q];
            ac[q>>1] += qv.x*kv.x + qv.y*kv.y + qv.z*kv.z + qv.w*kv.w;
        }

        #pragma unroll
        for (int h = 0; h < HH; h++) {
            float a = fminf(fmaxf(ac[h]*scale, -5.f), 5.f);
            sElog[h*520 + j] = a + Eh[h];
            gacc[h] += 1.f/(1.f + expf(-Gh[h]));
        }
    }

    #pragma unroll
    for (int h = 0; h < HH; h++) {
        #pragma unroll
        for (int off = 16; off > 0; off >>= 1)
            gacc[h] += __shfl_xor_sync(0xffffffffu, gacc[h], off);
    }
    if (lane == 0) {
        #pragma unroll
        for (int h = 0; h < HH; h++) sWpart[warp*8 + h] = gacc[h];
    }
    __syncthreads();
    if (tid < 8) {
        float s = 0.f;
        #pragma unroll
        for (int w = 0; w < 8; w++) s += sWpart[w*8 + tid];
        sCent[tid] = log1pf(s);
    }
    __syncthreads();

    {
        const int h = warp;
        const float* el = sElog + h*520;
        float mmax = -1e30f;
        for (int j = lane; j < NN; j += 32) mmax = fmaxf(mmax, el[j]);
        #pragma unroll
        for (int off = 16; off > 0; off >>= 1)
            mmax = fmaxf(mmax, __shfl_xor_sync(0xffffffffu, mmax, off));

        float denom = 0.f;
        float p0=0,p1=0,p2=0,p3=0,p4=0,p5=0,p6=0,p7=0;
        for (int j = lane; j < NN; j += 32) {
            float t = expf(el[j] - mmax);
            denom += t;
            const float4* vp = (const float4*)(g_v + (b*NN + j)*DD + h*8);
            float4 va = vp[0], vb = vp[1];
            p0 += t*va.x; p1 += t*va.y; p2 += t*va.z; p3 += t*va.w;
            p4 += t*vb.x; p5 += t*vb.y; p6 += t*vb.z; p7 += t*vb.w;
        }
        #pragma unroll
        for (int off = 16; off > 0; off >>= 1) {
            denom += __shfl_xor_sync(0xffffffffu, denom, off);
            p0 += __shfl_xor_sync(0xffffffffu, p0, off);
            p1 += __shfl_xor_sync(0xffffffffu, p1, off);
            p2 += __shfl_xor_sync(0xffffffffu, p2, off);
            p3 += __shfl_xor_sync(0xffffffffu, p3, off);
            p4 += __shfl_xor_sync(0xffffffffu, p4, off);
            p5 += __shfl_xor_sync(0xffffffffu, p5, off);
            p6 += __shfl_xor_sync(0xffffffffu, p6, off);
            p7 += __shfl_xor_sync(0xffffffffu, p7, off);
        }
        if (lane == 0) {
            float c = sCent[h] / denom;
            float* dst = g_vc + rowbn*DD + h*8;
            dst[0]=p0*c; dst[1]=p1*c; dst[2]=p2*c; dst[3]=p3*c;
            dst[4]=p4*c; dst[5]=p5*c; dst[6]=p6*c; dst[7]=p7*c;
        }
    }

    #pragma unroll
    for (int jj = 0; jj < 2; jj++) {
        const int j = tid + jj*256;
        float xv[64];
        const float4* xp = (const float4*)(erow + j*DD);
        #pragma unroll
        for (int q = 0; q < 16; q++) {
            float4 t = xp[q];
            xv[q*4+0]=t.x; xv[q*4+1]=t.y; xv[q*4+2]=t.z; xv[q*4+3]=t.w;
        }
        float s0=0,s1=0,s2=0,s3=0;
        #pragma unroll
        for (int k = 0; k < 64; k += 4) { s0+=xv[k]; s1+=xv[k+1]; s2+=xv[k+2]; s3+=xv[k+3]; }
        float m = ((s0+s1)+(s2+s3))*(1.f/64.f);
        float v0=0,v1=0,v2=0,v3=0;
        #pragma unroll
        for (int k = 0; k < 64; k += 4) {
            float d0=xv[k]-m, d1=xv[k+1]-m, d2=xv[k+2]-m, d3=xv[k+3]-m;
            v0+=d0*d0; v1+=d1*d1; v2+=d2*d2; v3+=d3*d3;
        }
        float rstd = rsqrtf(((v0+v1)+(v2+v3))*(1.f/64.f) + 1e-5f);

        float el[HH];
        #pragma unroll
        for (int h = 0; h < HH; h++) el[h] = sElog[h*520 + j];

        float ee[64];
        #pragma unroll
        for (int k = 0; k < 64; k++) {
            float e1 = (xv[k]-m)*rstd*sG1[k] + sBe1[k];
            float a = e1;
            #pragma unroll
            for (int h = 0; h < HH; h++) a += el[h]*sWoE[h*64 + k];
            ee[k] = a;
        }
        s0=s1=s2=s3=0;
        #pragma unroll
        for (int k = 0; k < 64; k += 4) { s0+=ee[k]; s1+=ee[k+1]; s2+=ee[k+2]; s3+=ee[k+3]; }
        float m2 = ((s0+s1)+(s2+s3))*(1.f/64.f);
        v0=v1=v2=v3=0;
        #pragma unroll
        for (int k = 0; k < 64; k += 4) {
            float d0=ee[k]-m2, d1=ee[k+1]-m2, d2=ee[k+2]-m2, d3=ee[k+3]-m2;
            v0+=d0*d0; v1+=d1*d1; v2+=d2*d2; v3+=d3*d3;
        }
        float rstd2 = rsqrtf(((v0+v1)+(v2+v3))*(1.f/64.f) + 1e-5f);
        #pragma unroll
        for (int k = 0; k < 64; k++)
            ee[k] = (ee[k]-m2)*rstd2*sG2[k] + sBe2[k];

        float out[64];
        #pragma unroll
        for (int k = 0; k < 64; k++) out[k] = sB2[k];

        #pragma unroll 2
        for (int u = 0; u < DHH; u++) {
            const float4* w1 = (const float4*)(sW1 + u*64);
            float ha=0,hb=0,hc=0,hd=0;
            #pragma unroll
            for (int q = 0; q < 16; q++) {
                float4 w = w1[q];
                ha += ee[q*4+0]*w.x;
                hb += ee[q*4+1]*w.y;
                hc += ee[q*4+2]*w.z;
                hd += ee[q*4+3]*w.w;
            }
            float hv = fmaxf(sB1[u] + ((ha+hb)+(hc+hd)), 0.f);
            const float4* w2 = (const float4*)(sW2 + u*64);
            #pragma unroll
            for (int q = 0; q < 16; q++) {
                float4 w = w2[q];
                out[q*4+0] += hv*w.x;
                out[q*4+1] += hv*w.y;
                out[q*4+2] += hv*w.z;
                out[q*4+3] += hv*w.w;
            }
        }

        float4* op = (float4*)(e_out + ((size_t)rowbn*NN + j)*DD);
        #pragma unroll
        for (int q = 0; q < 16; q++) {
            float4 r;
            r.x = ee[q*4+0] + fmaxf(out[q*4+0], 0.f);
            r.y = ee[q*4+1] + fmaxf(out[q*4+1], 0.f);
            r.z = ee[q*4+2] + fmaxf(out[q*4+2], 0.f);
            r.w = ee[q*4+3] + fmaxf(out[q*4+3], 0.f);
            op[q] = r;
        }
    }
}

__global__ void k_node_finish(const float* __restrict__ Wo_n,
                              const float* __restrict__ lng,
                              const float* __restrict__ lnb,
                              const float* __restrict__ W1,
                              const float* __restrict__ Bi1,
                              const float* __restrict__ W2,
                              const float* __restrict__ Bi2,
                              float* __restrict__ n_out)
{
    int row = blockIdx.x;
    int o = threadIdx.x;
    __shared__ float svc[DD];
    __shared__ float sn2[DD];
    __shared__ float sn3[DD];
    __shared__ float sh[DHH];
    svc[o] = g_vc[row*DD + o];
    __syncthreads();
    float acc = 0.f;
    #pragma unroll
    for (int k = 0; k < DD; k++) acc += svc[k]*Wo_n[k*DD + o];
    float n2 = g_n1[row*DD + o] + acc;
    sn2[o] = n2;
    __syncthreads();
    float s = 0.f;
    #pragma unroll
    for (int k = 0; k < DD; k++) s += sn2[k];
    float m = s*(1.f/DD);
    float v = 0.f;
    #pragma unroll
    for (int k = 0; k < DD; k++) { float d = sn2[k]-m; v += d*d; }
    v *= (1.f/DD);
    float rstd = rsqrtf(v + 1e-5f);
    float n3 = (n2-m)*rstd*lng[o] + lnb[o];
    sn3[o] = n3;
    __syncthreads();
    #pragma unroll
    for (int uu = 0; uu < 2; uu++) {
        int u = o + uu*64;
        float h = Bi1[u];
        #pragma unroll
        for (int k = 0; k < DD; k++) h += sn3[k]*W1[k*DHH + u];
        sh[u] = fmaxf(h, 0.f);
    }
    __syncthreads();
    float oacc = Bi2[o];
    #pragma unroll
    for (int u = 0; u < DHH; u++) oacc += sh[u]*W2[u*DD + o];
    n_out[row*DD + o] = n3 + fmaxf(oacc, 0.f);
}

extern "C" void kernel_launch(void* const* d_in, const int* in_sizes, int n_in,
                              void* d_out, int out_size)
{
    const float* n       = (const float*)d_in[0];
    const float* e       = (const float*)d_in[1];
    const float* Wq      = (const float*)d_in[2];
    const float* Wk      = (const float*)d_in[3];
    const float* Wv      = (const float*)d_in[4];
    const float* Wo_n    = (const float*)d_in[5];
    const float* We      = (const float*)d_in[6];
    const float* Wg      = (const float*)d_in[7];
    const float* Wo_e    = (const float*)d_in[8];
    const float* ln_n1_g = (const float*)d_in[9];
    const float* ln_n1_b = (const float*)d_in[10];
    const float* ln_e1_g = (const float*)d_in[11];
    const float* ln_e1_b = (const float*)d_in[12];
    const float* ln_n2_g = (const float*)d_in[13];
    const float* ln_n2_b = (const float*)d_in[14];
    const float* ln_e2_g = (const float*)d_in[15];
    const float* ln_e2_b = (const float*)d_in[16];
    const float* mn_w1   = (const float*)d_in[17];
    const float* mn_b1   = (const float*)d_in[18];
    const float* mn_w2   = (const float*)d_in[19];
    const float* mn_b2   = (const float*)d_in[20];
    const float* me_w1   = (const float*)d_in[21];
    const float* me_b1   = (const float*)d_in[22];
    const float* me_w2   = (const float*)d_in[23];
    const float* me_b2   = (const float*)d_in[24];

    float* out   = (float*)d_out;
    float* n_out = out;
    float* e_out = out + BB*NN*DD;

    cudaFuncSetAttribute(k_edge, cudaFuncAttributeMaxDynamicSharedMemorySize, SMEM_BYTES);

    k_node_prep<<<BB*NN, 64>>>(n, Wq, Wk, Wv, ln_n1_g, ln_n1_b);

    dim3 grid(NN, BB);
    k_edge<<<grid, 256, SMEM_BYTES>>>(e, We, Wg, Wo_e,
                                      ln_e1_g, ln_e1_b, ln_e2_g, ln_e2_b,
                                      me_w1, me_b1, me_w2, me_b2,
                                      e_out);

    k_node_finish<<<BB*NN, 64>>>(Wo_n, ln_n2_g, ln_n2_b,
                                 mn_w1, mn_b1, mn_w2, mn_b2, n_out);
}